// round 13
// baseline (speedup 1.0000x reference)
#include <cuda_runtime.h>

// Ende_3332894622093: B=65536, D=40, HB=20.
// out = [t1 | s2] (B,1,40);  J_T (B,40,40) =
//   [[diag(e4)+JJ12@J21, JJ12*e2], [J21, diag(e2)]]
// d_out: out flattened (n*40) then J_T flattened (n*1600).
//
// R13: quad lane tiling for phase D/E. Lane j -> (g=j/4: cols c4=4g..4g+3,
// q=j%4: rows q*5..q*5+4). jjt staged transposed + quarter-packed per row:
// [i0..3][i5..8][i10..13][i15..18][i4,i9,i14,i19], stride 20 floats, so the
// mainloop reads one f4 + one f1 per k, bank-complementary across the two
// items in a warp. One STG.128 per k-pair writes two complete bottom rows;
// top epilogue pairs quarter q with q^1 for TL/TR full rows.

#define IPB 8             // items per block
#define TPB (IPB * 20)    // 160 threads
#define WSS 560           // per-item smem stride (floats); 560 mod 32 = 16
#define XS  0
#define BB  40
#define S2  80
#define E2  100
#define E4  120
#define JJT 144           // jjt: 20 rows x 20 floats (quarter-packed)

__device__ __forceinline__ float tanh_fast(float x) {
    float r;
    asm("tanh.approx.f32 %0, %1;" : "=f"(r) : "f"(x));
    return r;
}

__global__ __launch_bounds__(TPB, 5)
void ende_kernel(const float* __restrict__ src,
                 const float* __restrict__ w1,
                 const float* __restrict__ w2,
                 const float* __restrict__ w3,
                 const float* __restrict__ w4,
                 float* __restrict__ outp,
                 float* __restrict__ jt,
                 int n)
{
    __shared__ float w1s[400], w2s[400], w3s[400], w4s[400];
    __shared__ __align__(16) float ws[IPB * WSS];

    const int tid = threadIdx.x;
    for (int i = tid; i < 400; i += TPB) {
        w1s[i] = w1[i];
        w2s[i] = w2[i];
        w3s[i] = w3[i];
        w4s[i] = w4[i];
    }

    const int itemL = tid / 20;
    const int j     = tid % 20;
    const int b     = blockIdx.x * IPB + itemL;
    const bool act  = (b < n);
    float* S = &ws[itemL * WSS];

    // ---- cooperative x load ----
    if (tid < IPB * 10) {
        int it = tid / 10, c = tid % 10;
        if (blockIdx.x * IPB + it < n) {
            float4 v = ((const float4*)(src + (size_t)(blockIdx.x * IPB + it) * 40))[c];
            *(float4*)&ws[it * WSS + c * 4] = v;
        }
    }
    __syncthreads();

    // ---- phase B: f1, f2, e2, (b1,b2), s2 ----
    float s2j;
    {
        float acc1 = 0.f, acc2 = 0.f;
        const float4* xv  = (const float4*)&S[XS];
        const float4* w1r = (const float4*)&w1s[j * 20];
        const float4* w2r = (const float4*)&w2s[j * 20];
        #pragma unroll
        for (int k4 = 0; k4 < 5; k4++) {
            float4 xx = xv[k4], a = w1r[k4], c = w2r[k4];
            acc1 += xx.x * a.x + xx.y * a.y + xx.z * a.z + xx.w * a.w;
            acc2 += xx.x * c.x + xx.y * c.y + xx.z * c.z + xx.w * c.w;
        }
        float f1 = tanh_fast(acc1);
        float f2 = tanh_fast(acc2);
        float e2 = __expf(f2);
        float p2  = S[XS + 20 + j];
        float p2e = p2 * e2;
        s2j = p2e + f1;
        ((float2*)&S[BB])[j] = make_float2(1.f - f1 * f1, p2e * (1.f - f2 * f2));
        S[S2 + j] = s2j;
        S[E2 + j] = e2;
    }
    __syncthreads();

    // ---- phase C: f3, f4, e4, t1, JJ12 row j -> jjt (transposed, packed) ----
    {
        float acc3 = 0.f, acc4 = 0.f;
        const float4* sv  = (const float4*)&S[S2];
        const float4* w3r = (const float4*)&w3s[j * 20];
        const float4* w4r = (const float4*)&w4s[j * 20];
        #pragma unroll
        for (int k4 = 0; k4 < 5; k4++) {
            float4 xx = sv[k4], a = w3r[k4], c = w4r[k4];
            acc3 += xx.x * a.x + xx.y * a.y + xx.z * a.z + xx.w * a.w;
            acc4 += xx.x * c.x + xx.y * c.y + xx.z * c.z + xx.w * c.w;
        }
        float f3 = tanh_fast(acc3);
        float f4 = tanh_fast(acc4);
        float e4 = __expf(f4);
        float s1  = S[XS + j];
        float s1e = s1 * e4;
        float a3 = 1.f - f3 * f3;
        float a4 = s1e * (1.f - f4 * f4);
        // packed position of column j within each jjt row
        const int pos = ((j % 5) < 4) ? (j / 5) * 4 + (j % 5) : 16 + (j / 5);
        #pragma unroll
        for (int k4 = 0; k4 < 5; k4++) {
            float4 a_ = w3r[k4], c_ = w4r[k4];
            S[JJT + (4 * k4 + 0) * 20 + pos] = a3 * a_.x + a4 * c_.x;
            S[JJT + (4 * k4 + 1) * 20 + pos] = a3 * a_.y + a4 * c_.y;
            S[JJT + (4 * k4 + 2) * 20 + pos] = a3 * a_.z + a4 * c_.z;
            S[JJT + (4 * k4 + 3) * 20 + pos] = a3 * a_.w + a4 * c_.w;
        }
        S[E4 + j] = e4;
        if (act) {
            outp[(size_t)b * 40 + j]      = s1e + f3;  // t1
            outp[(size_t)b * 40 + 20 + j] = s2j;
        }
    }
    __syncthreads();

    float* J = jt + (size_t)b * 1600;
    const int q  = j & 3;       // row quarter
    const int g  = j >> 2;      // col group
    const int c4 = g * 4;

    const float4 e2v = *(const float4*)&S[E2 + c4];
    const float4 e4v = *(const float4*)&S[E4 + c4];

    // hoisted bottom store pointer: rows 20+2kk+(q>>1), col (q&1 ? 20 : 0)+c4
    float* PB = J + (20 + (q >> 1)) * 40 + ((q & 1) ? 20 : 0) + c4;

    float4 acc[5];
    #pragma unroll
    for (int r = 0; r < 5; r++) acc[r] = make_float4(0.f, 0.f, 0.f, 0.f);

    // ---- fused D/E mainloop: 2 k per iteration, 1 full-double-row store ----
    #pragma unroll
    for (int kk = 0; kk < 10; kk++) {
        const float4 bbp = *(const float4*)&S[BB + 4 * kk];
        const int k0 = 2 * kk, k1 = 2 * kk + 1;

        // k0 (even)
        float4 wa = *(const float4*)&w1s[k0 * 20 + c4];
        float4 wb = *(const float4*)&w2s[k0 * 20 + c4];
        float4 m0;
        m0.x = bbp.x * wa.x + bbp.y * wb.x;
        m0.y = bbp.x * wa.y + bbp.y * wb.y;
        m0.z = bbp.x * wa.z + bbp.y * wb.z;
        m0.w = bbp.x * wa.w + bbp.y * wb.w;
        {
            const float* jr = &S[JJT + k0 * 20];
            float4 ja = *(const float4*)(jr + q * 4);
            float  js = jr[16 + q];
            acc[0].x += ja.x * m0.x; acc[0].y += ja.x * m0.y; acc[0].z += ja.x * m0.z; acc[0].w += ja.x * m0.w;
            acc[1].x += ja.y * m0.x; acc[1].y += ja.y * m0.y; acc[1].z += ja.y * m0.z; acc[1].w += ja.y * m0.w;
            acc[2].x += ja.z * m0.x; acc[2].y += ja.z * m0.y; acc[2].z += ja.z * m0.z; acc[2].w += ja.z * m0.w;
            acc[3].x += ja.w * m0.x; acc[3].y += ja.w * m0.y; acc[3].z += ja.w * m0.z; acc[3].w += ja.w * m0.w;
            acc[4].x += js   * m0.x; acc[4].y += js   * m0.y; acc[4].z += js   * m0.z; acc[4].w += js   * m0.w;
        }

        // k1 (odd)
        wa = *(const float4*)&w1s[k1 * 20 + c4];
        wb = *(const float4*)&w2s[k1 * 20 + c4];
        float4 m1;
        m1.x = bbp.z * wa.x + bbp.w * wb.x;
        m1.y = bbp.z * wa.y + bbp.w * wb.y;
        m1.z = bbp.z * wa.z + bbp.w * wb.z;
        m1.w = bbp.z * wa.w + bbp.w * wb.w;
        {
            const float* jr = &S[JJT + k1 * 20];
            float4 ja = *(const float4*)(jr + q * 4);
            float  js = jr[16 + q];
            acc[0].x += ja.x * m1.x; acc[0].y += ja.x * m1.y; acc[0].z += ja.x * m1.z; acc[0].w += ja.x * m1.w;
            acc[1].x += ja.y * m1.x; acc[1].y += ja.y * m1.y; acc[1].z += ja.y * m1.z; acc[1].w += ja.y * m1.w;
            acc[2].x += ja.z * m1.x; acc[2].y += ja.z * m1.y; acc[2].z += ja.z * m1.z; acc[2].w += ja.z * m1.w;
            acc[3].x += ja.w * m1.x; acc[3].y += ja.w * m1.y; acc[3].z += ja.w * m1.z; acc[3].w += ja.w * m1.w;
            acc[4].x += js   * m1.x; acc[4].y += js   * m1.y; acc[4].z += js   * m1.z; acc[4].w += js   * m1.w;
        }

        // one store: q0 -> BL row 20+k0, q1 -> BR row 20+k0,
        //            q2 -> BL row 20+k1, q3 -> BR row 20+k1
        {
            float4 br0 = make_float4((c4     == k0) ? e2v.x : 0.f,
                                     (c4 + 1 == k0) ? e2v.y : 0.f,
                                     (c4 + 2 == k0) ? e2v.z : 0.f,
                                     (c4 + 3 == k0) ? e2v.w : 0.f);
            float4 br1 = make_float4((c4     == k1) ? e2v.x : 0.f,
                                     (c4 + 1 == k1) ? e2v.y : 0.f,
                                     (c4 + 2 == k1) ? e2v.z : 0.f,
                                     (c4 + 3 == k1) ? e2v.w : 0.f);
            float4 v = (q == 0) ? m0 : (q == 1) ? br0 : (q == 2) ? m1 : br1;
            if (act) __stcs((float4*)&PB[kk * 80], v);
        }
    }

    // ---- diagonal into TL accumulators ----
    #pragma unroll
    for (int r = 0; r < 5; r++) {
        const int i = q * 5 + r;
        acc[r].x += (c4     == i) ? e4v.x : 0.f;
        acc[r].y += (c4 + 1 == i) ? e4v.y : 0.f;
        acc[r].z += (c4 + 2 == i) ? e4v.z : 0.f;
        acc[r].w += (c4 + 3 == i) ? e4v.w : 0.f;
    }

    // ---- TR segments for partner quarter sq = q^1 (rows sq*5..sq*5+4) ----
    const int sq = q ^ 1;
    float4 sg0, sg1, sg2, sg3;
    float  ss0, ss1, ss2, ss3;
    {
        const float* r0 = &S[JJT + (c4    ) * 20];
        const float* r1 = &S[JJT + (c4 + 1) * 20];
        const float* r2 = &S[JJT + (c4 + 2) * 20];
        const float* r3 = &S[JJT + (c4 + 3) * 20];
        sg0 = *(const float4*)(r0 + sq * 4); ss0 = r0[16 + sq];
        sg1 = *(const float4*)(r1 + sq * 4); ss1 = r1[16 + sq];
        sg2 = *(const float4*)(r2 + sq * 4); ss2 = r2[16 + sq];
        sg3 = *(const float4*)(r3 + sq * 4); ss3 = r3[16 + sq];
    }

    // ---- top stores: 2 instrs per r, each writing 2 complete rows ----
    // instr A row (q>>1)*10 + r:      q even -> TL acc[r], q odd -> TR row
    // instr B row 5 + (q>>1)*10 + r:  q odd  -> TL acc[r], q even -> TR row
    float* PA  = J + ((q >> 1) * 10) * 40 + ((q & 1) ? 20 : 0) + c4;
    float* PBt = J + (5 + (q >> 1) * 10) * 40 + ((q & 1) ? 0 : 20) + c4;
    if (act) {
        #pragma unroll
        for (int r = 0; r < 5; r++) {
            float4 tr;
            tr.x = ((r < 4) ? ((const float*)&sg0)[r] : ss0) * e2v.x;
            tr.y = ((r < 4) ? ((const float*)&sg1)[r] : ss1) * e2v.y;
            tr.z = ((r < 4) ? ((const float*)&sg2)[r] : ss2) * e2v.z;
            tr.w = ((r < 4) ? ((const float*)&sg3)[r] : ss3) * e2v.w;
            float4 vA = (q & 1) ? tr : acc[r];
            float4 vB = (q & 1) ? acc[r] : tr;
            __stcs((float4*)&PA[r * 40], vA);
            __stcs((float4*)&PBt[r * 40], vB);
        }
    }
}

extern "C" void kernel_launch(void* const* d_in, const int* in_sizes, int n_in,
                              void* d_out, int out_size)
{
    const float* src = (const float*)d_in[0];
    const float* w1  = (const float*)d_in[1];
    const float* w2  = (const float*)d_in[2];
    const float* w3  = (const float*)d_in[3];
    const float* w4  = (const float*)d_in[4];

    int n = in_sizes[0] / 40;
    float* outp = (float*)d_out;
    float* jt   = (float*)d_out + (size_t)n * 40;

    int blocks = (n + IPB - 1) / IPB;
    ende_kernel<<<blocks, TPB>>>(src, w1, w2, w3, w4, outp, jt, n);
}